// round 15
// baseline (speedup 1.0000x reference)
#include <cuda_runtime.h>
#include <cuda_fp16.h>
#include <cstdint>

// InstantNGP hash embedding. Only levels 0..7 contribute to out[:, :16].
// Resolutions R: 16,20,25,32,40,50,64,80.
//
//   stage A (fused, 16^3 tiles): per 16x16x16-cell tile, hash-gather the
//            (clamped) 17^3 corner lattice into smem, pack up to 4096 cells.
//            Cell = 32B, FEATURE-SPLIT: [feat0 of 8 corners fp16*2^13][feat1].
//   stage B: 2 threads per point (one per feature half); pair fetches the two
//            16B halves of one cell with one LDG.128 (same 128B line = the
//            structural floor of 8 line-touches/point). Results staged in
//            padded smem, coalesced float4 writeback.

#define N_POINTS   1048576
#define LOG2_T     19
#define TABLE_SIZE (1u << LOG2_T)
#define TABLE_MASK (TABLE_SIZE - 1u)
#define NLV 8

#define P1 2654435761u
#define P2 805459861u

#define FSCALE     8192.0f          // 2^13 exact
#define INV_FSCALE 1.220703125e-4f  // 2^-13 exact

// cells per axis D=R+1 (floor can reach R at x==1)
#define TOTAL_CELLS 1075325

__device__ uint4 g_cube[(size_t)TOTAL_CELLS * 2];   // 32B per cell

__constant__ int c_R[NLV]        = {16, 20, 25, 32, 40, 50, 64, 80};
__constant__ int c_cellOff[NLV]  = {0, 4913, 14174, 31750, 67687, 136608, 269259, 543884};
// 16^3-cell tiles: tiles per axis = ceil((R+1)/16); cumulative tile counts
__constant__ int c_TD16[NLV]     = {2, 2, 2, 3, 3, 4, 5, 6};
__constant__ int c_tileOff16[NLV]= {0, 8, 16, 24, 51, 78, 142, 267};
#define TOTAL_TILES16 483

// ---- stage A: fused gather + feature-split cell assembly (16^3 tiles) -----
__global__ __launch_bounds__(512) void build_cube_fused(const float* __restrict__ tables)
{
    __shared__ float2 sc[17 * 17 * 17];   // 39304B corner lattice

    int b = blockIdx.x;
    int lvl = 0;
    #pragma unroll
    for (int l = 1; l < NLV; ++l)
        if (b >= c_tileOff16[l]) lvl = l;
    b -= c_tileOff16[lvl];

    const int TD = c_TD16[lvl];
    const int tz = b % TD;
    const int tt = b / TD;
    const int ty = tt % TD;
    const int tx = tt / TD;

    const int R = c_R[lvl];
    const int D = R + 1;          // cells per axis
    const int G = D + 1;          // corners per axis
    const int tid = threadIdx.x;

    // clamped corner-region extents for this tile
    const int sx = min(17, G - 16 * tx);
    const int sy = min(17, G - 16 * ty);
    const int sz = min(17, G - 16 * tz);

    const float2* __restrict__ T =
        (const float2*)(tables + (size_t)lvl * TABLE_SIZE * 2);

    for (int idx = tid; idx < 17 * 17 * 17; idx += 512) {
        const int jx = idx / 289;
        const int jy = (idx / 17) % 17;
        const int jz = idx % 17;
        if (jx < sx && jy < sy && jz < sz) {
            const uint32_t gx = (uint32_t)(tx * 16 + jx);
            const uint32_t gy = (uint32_t)(ty * 16 + jy);
            const uint32_t gz = (uint32_t)(tz * 16 + jz);
            const uint32_t h = (gx ^ (gy * P1) ^ (gz * P2)) & TABLE_MASK;
            sc[idx] = __ldg(T + h);
        }
    }
    __syncthreads();

    for (int c = tid; c < 4096; c += 512) {
        const int ix = c >> 8;
        const int iy = (c >> 4) & 15;
        const int iz = c & 15;
        const int bx = tx * 16 + ix;
        const int by = ty * 16 + iy;
        const int bz = tz * 16 + iz;
        if (bx >= D || by >= D || bz >= D) continue;

        // strides: x=289, y=17, z=1
        const int s = (ix * 17 + iy) * 17 + iz;
        const float2 e000 = sc[s];
        const float2 e001 = sc[s + 1];
        const float2 e010 = sc[s + 17];
        const float2 e011 = sc[s + 18];
        const float2 e100 = sc[s + 289];
        const float2 e101 = sc[s + 290];
        const float2 e110 = sc[s + 306];
        const float2 e111 = sc[s + 307];

        // feature-split pack: u0 = feat0 (x), u1 = feat1 (y)
        // half2 pairs are (dz=0, dz=1) for each (dx,dy)
        #define PKH(a, bq) __float22half2_rn(make_float2((a) * FSCALE, (bq) * FSCALE))
        __half2 a0 = PKH(e000.x, e001.x), a1 = PKH(e010.x, e011.x);
        __half2 a2 = PKH(e100.x, e101.x), a3 = PKH(e110.x, e111.x);
        __half2 b0 = PKH(e000.y, e001.y), b1 = PKH(e010.y, e011.y);
        __half2 b2 = PKH(e100.y, e101.y), b3 = PKH(e110.y, e111.y);
        #undef PKH

        const int cell = (bx * D + by) * D + bz;
        uint4* dst = g_cube + ((size_t)c_cellOff[lvl] + cell) * 2;
        dst[0] = make_uint4(*(uint32_t*)&a0, *(uint32_t*)&a1,
                            *(uint32_t*)&a2, *(uint32_t*)&a3);
        dst[1] = make_uint4(*(uint32_t*)&b0, *(uint32_t*)&b1,
                            *(uint32_t*)&b2, *(uint32_t*)&b3);
    }
}

// ---- stage B: 2 threads per point, smem result staging --------------------
#define PTS_PER_BLK 128
#define RES_PAD 20   // floats per point row in staging (16 used + 4 pad)

__global__ __launch_bounds__(256) void hash_embed_kernel(
    const float* __restrict__ x,
    float* __restrict__ out)
{
    __shared__ float s_res[PTS_PER_BLK * RES_PAD];  // 10240B

    const int tid  = threadIdx.x;
    const int p    = tid >> 1;     // local point 0..127
    const int feat = tid & 1;      // feature half

    // direct coord load (both threads of a pair read the same 12B; warp
    // footprint = 2 lines per instruction)
    const size_t gp = (size_t)blockIdx.x * PTS_PER_BLK + p;
    const float px = __ldg(x + gp * 3 + 0);
    const float py = __ldg(x + gp * 3 + 1);
    const float pz = __ldg(x + gp * 3 + 2);

    const float cx = fminf(fmaxf(px, 0.0f), 1.0f);
    const float cy = fminf(fmaxf(py, 0.0f), 1.0f);
    const float cz = fminf(fmaxf(pz, 0.0f), 1.0f);

    const float RES[NLV] = {16.f, 20.f, 25.f, 32.f, 40.f, 50.f, 64.f, 80.f};
    const int   IR[NLV]  = {16, 20, 25, 32, 40, 50, 64, 80};
    const int   OFF[NLV] = {0, 4913, 14174, 31750, 67687, 136608, 269259, 543884};

    #pragma unroll
    for (int l = 0; l < NLV; ++l) {
        const float R = RES[l];

        // multiply-based cell + weights (no fdiv); O(1e-7) off reference,
        // trilinear continuity makes boundary flips benign.
        const float fbx = floorf(cx * R);
        const float fby = floorf(cy * R);
        const float fbz = floorf(cz * R);
        const float wx = fmaf(px, R, -fbx);
        const float wy = fmaf(py, R, -fby);
        const float wz = fmaf(pz, R, -fbz);

        const int D    = IR[l] + 1;
        const int cell = ((int)fbx * D + (int)fby) * D + (int)fbz;

        // pair of adjacent threads: the two 16B feature halves share a 128B line
        const uint4 u = __ldg(g_cube + ((size_t)OFF[l] + cell) * 2 + feat);

        // half2 pairs: (dz=0, dz=1) for (dx,dy) = 00,01,10,11
        const float2 v00 = __half22float2(*(const __half2*)&u.x);
        const float2 v01 = __half22float2(*(const __half2*)&u.y);
        const float2 v10 = __half22float2(*(const __half2*)&u.z);
        const float2 v11 = __half22float2(*(const __half2*)&u.w);

        const float iwz = 1.0f - wz;
        const float iwy = 1.0f - wy;

        const float z00 = v00.x * iwz + v00.y * wz;   // x=0,y=0
        const float z01 = v01.x * iwz + v01.y * wz;   // x=0,y=1
        const float z10 = v10.x * iwz + v10.y * wz;   // x=1,y=0
        const float z11 = v11.x * iwz + v11.y * wz;   // x=1,y=1

        const float y0 = z00 * iwy + z01 * wy;
        const float y1 = z10 * iwy + z11 * wy;
        const float res = y0 * (1.0f - wx) + y1 * wx;

        s_res[p * RES_PAD + 2 * l + feat] = res * INV_FSCALE;
    }
    __syncthreads();

    // coalesced writeback — thread (q,h) moves 32B of point q
    const int q = tid >> 1;
    const int h = tid & 1;
    const float4 r0 = *(const float4*)&s_res[q * RES_PAD + h * 8 + 0];
    const float4 r1 = *(const float4*)&s_res[q * RES_PAD + h * 8 + 4];
    float4* dst = (float4*)(out + ((size_t)blockIdx.x * PTS_PER_BLK + q) * 16) + h * 2;
    dst[0] = r0;
    dst[1] = r1;
}

extern "C" void kernel_launch(void* const* d_in, const int* in_sizes, int n_in,
                              void* d_out, int out_size)
{
    const float* x      = (const float*)d_in[0];   // (N_POINTS, 3) f32
    const float* tables = (const float*)d_in[1];   // (16, TABLE_SIZE, 2) f32
    float* out          = (float*)d_out;           // (N_POINTS, 16) f32

    build_cube_fused<<<TOTAL_TILES16, 512>>>(tables);
    hash_embed_kernel<<<N_POINTS / PTS_PER_BLK, 256>>>(x, out);
}

// round 17
// speedup vs baseline: 1.6535x; 1.6535x over previous
#include <cuda_runtime.h>
#include <cuda_fp16.h>
#include <cstdint>

// InstantNGP hash embedding. Only levels 0..7 contribute to out[:, :16].
// Resolutions R: 16,20,25,32,40,50,64,80.
//
//   stage A (fused, 8^3 tiles — proven round-13 config): per 8x8x8-cell tile,
//            hash-gather the 9^3 corner lattice into smem, pack 512 cells.
//            Cell = 32B, FEATURE-SPLIT: [feat0 of 8 corners fp16*2^13][feat1].
//            Triggers PDL launch_dependents at CTA start.
//   stage B: 2 threads per point (one per feature half); PDL secondary —
//            stages coords into smem PRE-wait (overlaps stage A tail), then
//            griddepcontrol.wait, then the 8-level gather+trilerp. Pair of
//            adjacent threads fetches the two 16B halves of one cell with one
//            LDG.128 (same 128B line = structural floor of 8 touches/point).

#define N_POINTS   1048576
#define LOG2_T     19
#define TABLE_SIZE (1u << LOG2_T)
#define TABLE_MASK (TABLE_SIZE - 1u)
#define NLV 8

#define P1 2654435761u
#define P2 805459861u

#define FSCALE     8192.0f          // 2^13 exact
#define INV_FSCALE 1.220703125e-4f  // 2^-13 exact

// cells per axis D=R+1 (floor can reach R at x==1)
#define TOTAL_CELLS 1075325

__device__ uint4 g_cube[(size_t)TOTAL_CELLS * 2];   // 32B per cell

__constant__ int c_R[NLV]       = {16, 20, 25, 32, 40, 50, 64, 80};
__constant__ int c_cellOff[NLV] = {0, 4913, 14174, 31750, 67687, 136608, 269259, 543884};
// 8^3-cell tiles: tiles per axis = ceil((R+1)/8); cumulative tile counts
__constant__ int c_TD[NLV]      = {3, 3, 4, 5, 6, 7, 9, 11};
__constant__ int c_tileOff[NLV] = {0, 27, 54, 118, 243, 459, 802, 1531};
#define TOTAL_TILES 2862

// ---- stage A: fused gather + feature-split cell assembly ------------------
__global__ __launch_bounds__(256) void build_cube_fused(const float* __restrict__ tables)
{
    // allow the dependent kernel to begin its pre-wait phase immediately
    asm volatile("griddepcontrol.launch_dependents;");

    __shared__ float2 sc[9 * 9 * 9];   // 5832B corner lattice

    int b = blockIdx.x;
    int lvl = 0;
    #pragma unroll
    for (int l = 1; l < NLV; ++l)
        if (b >= c_tileOff[l]) lvl = l;
    b -= c_tileOff[lvl];

    const int TD = c_TD[lvl];
    const int tz = b % TD;
    const int tt = b / TD;
    const int ty = tt % TD;
    const int tx = tt / TD;

    const int R = c_R[lvl];
    const int D = R + 1;
    const int tid = threadIdx.x;

    const float2* __restrict__ T =
        (const float2*)(tables + (size_t)lvl * TABLE_SIZE * 2);

    for (int idx = tid; idx < 729; idx += 256) {
        const int jz = idx % 9;
        const int jt = idx / 9;
        const int jy = jt % 9;
        const int jx = jt / 9;
        const uint32_t gx = (uint32_t)(tx * 8 + jx);
        const uint32_t gy = (uint32_t)(ty * 8 + jy);
        const uint32_t gz = (uint32_t)(tz * 8 + jz);
        const uint32_t h = (gx ^ (gy * P1) ^ (gz * P2)) & TABLE_MASK;
        sc[idx] = __ldg(T + h);
    }
    __syncthreads();

    for (int c = tid; c < 512; c += 256) {
        const int iz = c & 7;
        const int iy = (c >> 3) & 7;
        const int ix = c >> 6;
        const int bx = tx * 8 + ix;
        const int by = ty * 8 + iy;
        const int bz = tz * 8 + iz;
        if (bx >= D || by >= D || bz >= D) continue;

        const int s = (ix * 9 + iy) * 9 + iz;
        const float2 e000 = sc[s];
        const float2 e001 = sc[s + 1];
        const float2 e010 = sc[s + 9];
        const float2 e011 = sc[s + 10];
        const float2 e100 = sc[s + 81];
        const float2 e101 = sc[s + 82];
        const float2 e110 = sc[s + 90];
        const float2 e111 = sc[s + 91];

        // feature-split pack: u0 = feat0 (x), u1 = feat1 (y)
        // half2 pairs are (dz=0, dz=1) for each (dx,dy)
        #define PKH(a, bq) __float22half2_rn(make_float2((a) * FSCALE, (bq) * FSCALE))
        __half2 a0 = PKH(e000.x, e001.x), a1 = PKH(e010.x, e011.x);
        __half2 a2 = PKH(e100.x, e101.x), a3 = PKH(e110.x, e111.x);
        __half2 b0 = PKH(e000.y, e001.y), b1 = PKH(e010.y, e011.y);
        __half2 b2 = PKH(e100.y, e101.y), b3 = PKH(e110.y, e111.y);
        #undef PKH

        const int cell = (bx * D + by) * D + bz;
        uint4* dst = g_cube + ((size_t)c_cellOff[lvl] + cell) * 2;
        dst[0] = make_uint4(*(uint32_t*)&a0, *(uint32_t*)&a1,
                            *(uint32_t*)&a2, *(uint32_t*)&a3);
        dst[1] = make_uint4(*(uint32_t*)&b0, *(uint32_t*)&b1,
                            *(uint32_t*)&b2, *(uint32_t*)&b3);
    }
}

// ---- stage B: 2 threads per point, PDL secondary --------------------------
#define PTS_PER_BLK 128
#define RES_PAD 20   // floats per point row in staging (16 used + 4 pad)

__global__ __launch_bounds__(256) void hash_embed_kernel(
    const float* __restrict__ x,
    float* __restrict__ out)
{
    __shared__ float s_x[PTS_PER_BLK * 3];          // 1536B
    __shared__ float s_res[PTS_PER_BLK * RES_PAD];  // 10240B

    const int tid  = threadIdx.x;
    const int p    = tid >> 1;     // local point 0..127
    const int feat = tid & 1;      // feature half

    // ---- pre-wait phase: coalesced coord staging (independent of g_cube) ----
    const float* xb = x + (size_t)blockIdx.x * (PTS_PER_BLK * 3);
    for (int idx = tid; idx < PTS_PER_BLK * 3; idx += 256)
        s_x[idx] = xb[idx];
    __syncthreads();

    const float px = s_x[p * 3 + 0];
    const float py = s_x[p * 3 + 1];
    const float pz = s_x[p * 3 + 2];

    const float cx = fminf(fmaxf(px, 0.0f), 1.0f);
    const float cy = fminf(fmaxf(py, 0.0f), 1.0f);
    const float cz = fminf(fmaxf(pz, 0.0f), 1.0f);

    // ---- wait for stage A's g_cube to be complete & visible ----
    asm volatile("griddepcontrol.wait;" ::: "memory");

    const float RES[NLV] = {16.f, 20.f, 25.f, 32.f, 40.f, 50.f, 64.f, 80.f};
    const int   IR[NLV]  = {16, 20, 25, 32, 40, 50, 64, 80};
    const int   OFF[NLV] = {0, 4913, 14174, 31750, 67687, 136608, 269259, 543884};

    #pragma unroll
    for (int l = 0; l < NLV; ++l) {
        const float R = RES[l];

        // multiply-based cell + weights (no fdiv); O(1e-7) off reference,
        // trilinear continuity makes boundary flips benign.
        const float fbx = floorf(cx * R);
        const float fby = floorf(cy * R);
        const float fbz = floorf(cz * R);
        const float wx = fmaf(px, R, -fbx);
        const float wy = fmaf(py, R, -fby);
        const float wz = fmaf(pz, R, -fbz);

        const int D    = IR[l] + 1;
        const int cell = ((int)fbx * D + (int)fby) * D + (int)fbz;

        // pair of adjacent threads: the two 16B feature halves share a 128B line
        const uint4 u = __ldg(g_cube + ((size_t)OFF[l] + cell) * 2 + feat);

        // half2 pairs: (dz=0, dz=1) for (dx,dy) = 00,01,10,11
        const float2 v00 = __half22float2(*(const __half2*)&u.x);
        const float2 v01 = __half22float2(*(const __half2*)&u.y);
        const float2 v10 = __half22float2(*(const __half2*)&u.z);
        const float2 v11 = __half22float2(*(const __half2*)&u.w);

        const float iwz = 1.0f - wz;
        const float iwy = 1.0f - wy;

        const float z00 = v00.x * iwz + v00.y * wz;   // x=0,y=0
        const float z01 = v01.x * iwz + v01.y * wz;   // x=0,y=1
        const float z10 = v10.x * iwz + v10.y * wz;   // x=1,y=0
        const float z11 = v11.x * iwz + v11.y * wz;   // x=1,y=1

        const float y0 = z00 * iwy + z01 * wy;
        const float y1 = z10 * iwy + z11 * wy;
        const float res = y0 * (1.0f - wx) + y1 * wx;

        s_res[p * RES_PAD + 2 * l + feat] = res * INV_FSCALE;
    }
    __syncthreads();

    // coalesced writeback — thread (q,h) moves 32B of point q
    const int q = tid >> 1;
    const int h = tid & 1;
    const float4 r0 = *(const float4*)&s_res[q * RES_PAD + h * 8 + 0];
    const float4 r1 = *(const float4*)&s_res[q * RES_PAD + h * 8 + 4];
    float4* dst = (float4*)(out + ((size_t)blockIdx.x * PTS_PER_BLK + q) * 16) + h * 2;
    dst[0] = r0;
    dst[1] = r1;
}

extern "C" void kernel_launch(void* const* d_in, const int* in_sizes, int n_in,
                              void* d_out, int out_size)
{
    const float* x      = (const float*)d_in[0];   // (N_POINTS, 3) f32
    const float* tables = (const float*)d_in[1];   // (16, TABLE_SIZE, 2) f32
    float* out          = (float*)d_out;           // (N_POINTS, 16) f32

    // stage A: primary
    build_cube_fused<<<TOTAL_TILES, 256>>>(tables);

    // stage B: PDL secondary — launches early, waits for A inside the kernel
    cudaLaunchConfig_t cfg = {};
    cfg.gridDim  = dim3(N_POINTS / PTS_PER_BLK);
    cfg.blockDim = dim3(256);
    cfg.dynamicSmemBytes = 0;
    cfg.stream = 0;
    cudaLaunchAttribute attrs[1];
    attrs[0].id = cudaLaunchAttributeProgrammaticStreamSerialization;
    attrs[0].val.programmaticStreamSerializationAllowed = 1;
    cfg.attrs = attrs;
    cfg.numAttrs = 1;
    cudaLaunchKernelEx(&cfg, hash_embed_kernel, x, out);
}